// round 16
// baseline (speedup 1.0000x reference)
#include <cuda_runtime.h>
#include <cuda_bf16.h>
#include <math.h>

// CropRoi: f (B=4, C=64, 32,32,32) f32; proposals (N,8) [b,score,cx,cy,cz,sx,sy,sz]
// out (N,C,7,7,7) f32. dims_max=32, R=7. L=c1-c0 in [2,13] => all bin widths in [1,3].
//
// Block = (proposal n, (i,j)): d/h bounds block-uniform. 4 warps x 16 channels.
// Lane = c_sub*8 + k (c_sub: channel slot, k: w-bin; 28 active lanes).
// No smem, no __syncthreads: each warp computes the 21 axis-bin bounds in-lane
// and distributes via shfl. d x h fully unrolled as a 3x3 predicated cell grid
// (uniform branches) -> all region loads batch before the FMAX tree.

#define R_BINS 7
#define C_CH   64
#define DIMMAX 32
#define NTHREADS 128
#define QS (4 * 32768)      // floats between 4-channel slots

__global__ __launch_bounds__(NTHREADS) void crop_roi_kernel(
        const float* __restrict__ f,
        const float* __restrict__ props,
        float* __restrict__ out) {
    const int n    = blockIdx.x;
    const int ij   = blockIdx.y;            // 0..48
    const int tid  = threadIdx.x;
    const int lane = tid & 31;
    const int warp = tid >> 5;

    const int i = ij / 7;
    const int j = ij - i * 7;

    // ---- per-warp bounds: lanes 0..20 compute (ax = t/7, bi = t%7) ----
    const float* p = props + (size_t)n * 8;
    const int b = (int)p[0];

    const int t  = (lane < 21) ? lane : 0;
    const int ax = t / 7;
    const int bi = t - ax * 7;
    float center = __ldg(p + 2 + ax);
    float side   = __ldg(p + 5 + ax);
    // *0.5f and *0.25f exact (powers of two) -> matches jnp arithmetic
    int c0 = (int)floorf((center - 0.5f * side) * 0.25f);
    int c1 = (int)ceilf ((center + 0.5f * side) * 0.25f);
    c0 = max(c0, 0);
    c1 = min(c1, DIMMAX);
    int L  = c1 - c0;
    int ss = c0 + (bi * L) / R_BINS;                     // floor div (magic mul)
    int ee = c0 + ((bi + 1) * L + R_BINS - 1) / R_BINS;  // ceil div
    ee = min(ee, ss + 6);                                // K cap (safety)

    // distribute: d-bounds from lane i, h-bounds from lane 7+j, w from 14+k
    const int k      = lane & 7;
    const bool active = (k < 7);
    const int kk     = active ? k : 0;

    const int sd = __shfl_sync(0xffffffffu, ss, i);
    const int nd = __shfl_sync(0xffffffffu, ee, i) - sd;        // 1..3
    const int sh = __shfl_sync(0xffffffffu, ss, 7 + j);
    const int nh = __shfl_sync(0xffffffffu, ee, 7 + j) - sh;    // 1..3
    const int w0 = __shfl_sync(0xffffffffu, ss, 14 + kk);
    const int ww = __shfl_sync(0xffffffffu, ee, 14 + kk) - w0;  // 1..3

    const int c_sub = lane >> 3;
    const int ch0   = warp * 16 + c_sub;
    const float* base = f + (((size_t)b * C_CH + ch0) << 15) + (sd << 10) + (sh << 5) + w0;

    const float NEG = -3.402823466e+38f;    // finfo(float32).min
    float m0 = NEG, m1 = NEG, m2 = NEG, m3 = NEG;

    // one (d,h) cell: 4 unconditional + 8 predicated loads, fixed imm offsets
#define CELL(OFF) do {                                         \
        const float* P = base + (OFF);                         \
        float a0 = P[0 * QS];                                  \
        float a1 = P[1 * QS];                                  \
        float a2 = P[2 * QS];                                  \
        float a3 = P[3 * QS];                                  \
        if (ww > 1) {                                          \
            a0 = fmaxf(a0, P[1 + 0 * QS]);                     \
            a1 = fmaxf(a1, P[1 + 1 * QS]);                     \
            a2 = fmaxf(a2, P[1 + 2 * QS]);                     \
            a3 = fmaxf(a3, P[1 + 3 * QS]);                     \
        }                                                      \
        if (ww > 2) {                                          \
            a0 = fmaxf(a0, P[2 + 0 * QS]);                     \
            a1 = fmaxf(a1, P[2 + 1 * QS]);                     \
            a2 = fmaxf(a2, P[2 + 2 * QS]);                     \
            a3 = fmaxf(a3, P[2 + 3 * QS]);                     \
        }                                                      \
        m0 = fmaxf(m0, a0);                                    \
        m1 = fmaxf(m1, a1);                                    \
        m2 = fmaxf(m2, a2);                                    \
        m3 = fmaxf(m3, a3);                                    \
    } while (0)

    // 3x3 (d,h) grid, warp-uniform guards (nd, nh in [1,3])
    CELL(0);
    if (nh > 1) CELL(32);
    if (nh > 2) CELL(64);
    if (nd > 1) {
        CELL(1024);
        if (nh > 1) CELL(1024 + 32);
        if (nh > 2) CELL(1024 + 64);
    }
    if (nd > 2) {
        CELL(2048);
        if (nh > 1) CELL(2048 + 32);
        if (nh > 2) CELL(2048 + 64);
    }
#undef CELL

    if (active) {
        size_t o = ((size_t)n * C_CH + ch0) * 343 + ij * 7 + k;
        out[o]            = m0;
        out[o +  4 * 343] = m1;
        out[o +  8 * 343] = m2;
        out[o + 12 * 343] = m3;
    }
}

extern "C" void kernel_launch(void* const* d_in, const int* in_sizes, int n_in,
                              void* d_out, int out_size) {
    const float* f     = (const float*)d_in[0];
    const float* props = (const float*)d_in[2];
    float* out = (float*)d_out;

    int n_props = in_sizes[2] / 8;
    dim3 grid(n_props, 49);
    crop_roi_kernel<<<grid, NTHREADS>>>(f, props, out);
}